// round 2
// baseline (speedup 1.0000x reference)
#include <cuda_runtime.h>
#include <math.h>

// GAT_15547781612261 — subgraph-pruned 3-layer GAT.
// Only the 3-hop reverse neighborhood of the 8 output nodes is computed.
// NOTE: edge_index / ptr are int32 (JAX default x64-disabled downcasts int64).

#define NN 8192
#define EE 32768
#define ET (EE + NN)   // real edges + self loops
#define HH 6

// ---------------- scratch (device globals; no allocation) ----------------
__device__ int g_flag0[NN], g_flag1[NN], g_flag2[NN], g_flag3[NN];
__device__ int g_list0[NN], g_list1[NN], g_list2[NN];
__device__ int g_pos0[NN], g_pos1[NN], g_pos2[NN], g_pos3[NN];
// g_cnt: 0..2 = node counts V0,V1,V2 ; 3..5 = edge counts layer1..3 ; 6 = 8 (V3)
__device__ int g_cnt[8];
__device__ int g_nodeB[8];
__device__ int g_e1s[ET], g_e1d[ET], g_e2s[ET], g_e2d[ET], g_e3s[ET], g_e3d[ET];
__device__ float g_A1[(size_t)NN * 768];
__device__ float g_A2[(size_t)NN * 1536];
__device__ float g_A3[(size_t)NN * 6168];
__device__ float g_h1[(size_t)NN * 128];
__device__ float g_h2[(size_t)NN * 256];
__device__ float g_es[NN * HH], g_ed[NN * HH];
__device__ unsigned g_mx[NN * HH];
__device__ float g_z[NN * HH];
__device__ float g_ew[(size_t)ET * HH];
__device__ float g_out3[8 * 1028];

// ---------------- helpers ----------------
__device__ __forceinline__ float* Ap(int L)   { return L == 0 ? g_A1 : (L == 1 ? g_A2 : g_A3); }
__device__ __forceinline__ int*   Esp(int L)  { return L == 0 ? g_e1s : (L == 1 ? g_e2s : g_e3s); }
__device__ __forceinline__ int*   Edp(int L)  { return L == 0 ? g_e1d : (L == 1 ? g_e2d : g_e3d); }
__device__ __forceinline__ int*   Pin(int L)  { return L == 0 ? g_pos0 : (L == 1 ? g_pos1 : g_pos2); }
__device__ __forceinline__ int*   Pout(int L) { return L == 0 ? g_pos1 : (L == 1 ? g_pos2 : g_pos3); }
__device__ __forceinline__ float* Hout(int L) { return L == 0 ? g_h1 : (L == 1 ? g_h2 : g_out3); }
__device__ __forceinline__ int    OutCnt(int L) { return g_cnt[L == 2 ? 6 : L + 1]; }
__device__ __forceinline__ int    Ecnt(int L)   { return g_cnt[3 + L]; }

// order-preserving float <-> uint for atomicMax segment-max
__device__ __forceinline__ unsigned fkey(float f) {
    unsigned b = __float_as_uint(f);
    return (b & 0x80000000u) ? ~b : (b | 0x80000000u);
}
__device__ __forceinline__ float fdec(unsigned k) {
    unsigned b = (k & 0x80000000u) ? (k & 0x7FFFFFFFu) : ~k;
    return __uint_as_float(b);
}

// ---------------- setup kernels ----------------
__global__ void reset_kernel() {
    int stride = gridDim.x * blockDim.x;
    for (int i = blockIdx.x * blockDim.x + threadIdx.x; i < NN; i += stride) {
        g_flag0[i] = 0; g_flag1[i] = 0; g_flag2[i] = 0; g_flag3[i] = 0;
        if (i < 8) g_cnt[i] = 0;
    }
}

__global__ void mark_kernel(const int* __restrict__ ptr) {
    int b = threadIdx.x;
    if (b == 0) g_cnt[6] = 8;
    if (b < 8) {
        int node = ptr[b + 1] - 1;
        g_nodeB[b] = node;
        g_pos3[node] = b;
        g_flag3[node] = 1; g_flag2[node] = 1; g_flag1[node] = 1; g_flag0[node] = 1;
    }
}

// level=3: flag3[dst] -> set flag2,flag1,flag0 at src. level=2: flag2 -> flag1,flag0. level=1: flag1 -> flag0.
__global__ void expand_kernel(const int* __restrict__ ei, int level) {
    int stride = gridDim.x * blockDim.x;
    for (int e = blockIdx.x * blockDim.x + threadIdx.x; e < EE; e += stride) {
        int s = ei[e];
        int d = ei[EE + e];
        if (level == 3) {
            if (g_flag3[d]) { g_flag2[s] = 1; g_flag1[s] = 1; g_flag0[s] = 1; }
        } else if (level == 2) {
            if (g_flag2[d]) { g_flag1[s] = 1; g_flag0[s] = 1; }
        } else {
            if (g_flag1[d]) { g_flag0[s] = 1; }
        }
    }
}

__global__ void compact_kernel() {
    int stride = gridDim.x * blockDim.x;
    for (int i = blockIdx.x * blockDim.x + threadIdx.x; i < NN; i += stride) {
        if (g_flag0[i]) { int j = atomicAdd(&g_cnt[0], 1); g_list0[j] = i; g_pos0[i] = j; }
        if (g_flag1[i]) { int j = atomicAdd(&g_cnt[1], 1); g_list1[j] = i; g_pos1[i] = j; }
        if (g_flag2[i]) { int j = atomicAdd(&g_cnt[2], 1); g_list2[j] = i; g_pos2[i] = j; }
    }
}

__global__ void build_edges_kernel(const int* __restrict__ ei) {
    int stride = gridDim.x * blockDim.x;
    for (int t = blockIdx.x * blockDim.x + threadIdx.x; t < ET; t += stride) {
        int s, d;
        if (t < EE) { s = ei[t]; d = ei[EE + t]; }
        else        { s = t - EE; d = t - EE; }           // self loop
        if (g_flag1[d]) { int j = atomicAdd(&g_cnt[3], 1); g_e1s[j] = s; g_e1d[j] = d; }
        if (g_flag2[d]) { int j = atomicAdd(&g_cnt[4], 1); g_e2s[j] = s; g_e2d[j] = d; }
        if (g_flag3[d]) { int j = atomicAdd(&g_cnt[5], 1); g_e3s[j] = s; g_e3d[j] = d; }
    }
}

// ---------------- GEMM: C[M, Ncol] = A[M(indirect), K] @ B[K, Ncol] ----------------
__global__ void gemm_kernel(int L, const float* __restrict__ Ax, const float* __restrict__ Bw,
                            int K, int Ncol) {
    __shared__ float As[16][64];
    __shared__ float Bs[16][64];
    int M = g_cnt[L];
    const float* A = (L == 0) ? Ax : (L == 1 ? g_h1 : g_h2);
    float* Cm = Ap(L);
    const int* rowList = (L == 0) ? g_list0 : (const int*)0;

    int numRowT = (M + 63) >> 6;
    int numColT = (Ncol + 63) >> 6;
    int nt = numRowT * numColT;
    int tid = threadIdx.x;
    int tx = tid & 15, ty = tid >> 4;
    int lm  = tid >> 2;          // A load: row in tile
    int lk  = (tid & 3) * 4;     // A load: k base
    int lkb = tid >> 4;          // B load: k
    int lc  = (tid & 15) * 4;    // B load: col base

    for (int t = blockIdx.x; t < nt; t += gridDim.x) {
        int rt = t / numColT, ct = t - rt * numColT;
        int row0 = rt * 64, col0 = ct * 64;
        int grow = row0 + lm;
        int arow = -1;
        if (grow < M) arow = rowList ? rowList[grow] : grow;

        float acc[4][4];
        #pragma unroll
        for (int i = 0; i < 4; i++)
            #pragma unroll
            for (int j = 0; j < 4; j++) acc[i][j] = 0.f;

        for (int k0 = 0; k0 < K; k0 += 16) {
            #pragma unroll
            for (int j = 0; j < 4; j++) {
                int k = lk + j;
                As[k][lm] = (arow >= 0 && (k0 + k) < K) ? A[(size_t)arow * K + k0 + k] : 0.f;
            }
            #pragma unroll
            for (int j = 0; j < 4; j++) {
                int c = lc + j;
                Bs[lkb][c] = ((k0 + lkb) < K && (col0 + c) < Ncol)
                               ? Bw[(size_t)(k0 + lkb) * Ncol + col0 + c] : 0.f;
            }
            __syncthreads();
            #pragma unroll
            for (int k = 0; k < 16; k++) {
                float a[4], b[4];
                #pragma unroll
                for (int i = 0; i < 4; i++) a[i] = As[k][ty * 4 + i];
                #pragma unroll
                for (int j = 0; j < 4; j++) b[j] = Bs[k][tx * 4 + j];
                #pragma unroll
                for (int i = 0; i < 4; i++)
                    #pragma unroll
                    for (int j = 0; j < 4; j++) acc[i][j] += a[i] * b[j];
            }
            __syncthreads();
        }
        #pragma unroll
        for (int i = 0; i < 4; i++) {
            int r = row0 + ty * 4 + i;
            if (r < M) {
                #pragma unroll
                for (int j = 0; j < 4; j++) {
                    int c = col0 + tx * 4 + j;
                    if (c < Ncol) Cm[(size_t)r * Ncol + c] = acc[i][j];
                }
            }
        }
    }
}

// es[i,h] = <A[i, h*Cout : ], a_src[h]>, ed likewise. One warp per row.
__global__ void coef_kernel(int L, const float* __restrict__ asr, const float* __restrict__ adr,
                            int Wcols, int Cout) {
    int M = g_cnt[L];
    const float* A = Ap(L);
    int warpId = (blockIdx.x * blockDim.x + threadIdx.x) >> 5;
    int lane = threadIdx.x & 31;
    int nwarp = (gridDim.x * blockDim.x) >> 5;
    for (int i = warpId; i < M; i += nwarp) {
        for (int h = 0; h < HH; h++) {
            const float* row = A + (size_t)i * Wcols + (size_t)h * Cout;
            const float* va = asr + (size_t)h * Cout;
            const float* vd = adr + (size_t)h * Cout;
            float s1 = 0.f, s2 = 0.f;
            for (int c = lane; c < Cout; c += 32) {
                float v = row[c];
                s1 += v * va[c];
                s2 += v * vd[c];
            }
            #pragma unroll
            for (int o = 16; o > 0; o >>= 1) {
                s1 += __shfl_down_sync(0xFFFFFFFFu, s1, o);
                s2 += __shfl_down_sync(0xFFFFFFFFu, s2, o);
            }
            if (lane == 0) { g_es[i * HH + h] = s1; g_ed[i * HH + h] = s2; }
        }
    }
}

__global__ void zero_layer_kernel(int L, int Cout) {
    int M = OutCnt(L);
    float* hout = Hout(L);
    int stride = gridDim.x * blockDim.x;
    int tid0 = blockIdx.x * blockDim.x + threadIdx.x;
    int totH = M * Cout;
    for (int t = tid0; t < totH; t += stride) hout[t] = 0.f;
    int totS = M * HH;
    for (int t = tid0; t < totS; t += stride) { g_mx[t] = 0u; g_z[t] = 0.f; }
}

__global__ void edge_pass1(int L, float slope) {
    int ne = Ecnt(L);
    const int* es_ = Esp(L); const int* ed_ = Edp(L);
    const int* pin = Pin(L); const int* pout = Pout(L);
    int total = ne * HH;
    int stride = gridDim.x * blockDim.x;
    for (int t = blockIdx.x * blockDim.x + threadIdx.x; t < total; t += stride) {
        int e = t / HH, h = t - e * HH;
        int s = es_[e], d = ed_[e];
        float v = g_es[pin[s] * HH + h] + g_ed[pin[d] * HH + h];
        v = (v >= 0.f) ? v : slope * v;
        g_ew[t] = v;
        atomicMax(&g_mx[pout[d] * HH + h], fkey(v));
    }
}

__global__ void edge_pass2(int L) {
    int ne = Ecnt(L);
    const int* ed_ = Edp(L);
    const int* pout = Pout(L);
    int total = ne * HH;
    int stride = gridDim.x * blockDim.x;
    for (int t = blockIdx.x * blockDim.x + threadIdx.x; t < total; t += stride) {
        int e = t / HH, h = t - e * HH;
        int d = ed_[e];
        float m = fdec(g_mx[pout[d] * HH + h]);
        float ex = expf(g_ew[t] - m);
        g_ew[t] = ex;
        atomicAdd(&g_z[pout[d] * HH + h], ex);
    }
}

__global__ void edge_alpha(int L) {
    int ne = Ecnt(L);
    const int* ed_ = Edp(L);
    const int* pout = Pout(L);
    int total = ne * HH;
    int stride = gridDim.x * blockDim.x;
    for (int t = blockIdx.x * blockDim.x + threadIdx.x; t < total; t += stride) {
        int e = t / HH, h = t - e * HH;
        int d = ed_[e];
        g_ew[t] = g_ew[t] * (1.0f / HH) / g_z[pout[d] * HH + h];   // alpha / heads
    }
}

__global__ void edge_pass3(int L, int Wcols, int Cout) {
    int ne = Ecnt(L);
    const int* es_ = Esp(L); const int* ed_ = Edp(L);
    const int* pin = Pin(L); const int* pout = Pout(L);
    const float* A = Ap(L);
    float* hout = Hout(L);
    int total = ne * Cout;
    int stride = gridDim.x * blockDim.x;
    for (int t = blockIdx.x * blockDim.x + threadIdx.x; t < total; t += stride) {
        int e = t / Cout, c = t - e * Cout;
        int s = es_[e], d = ed_[e];
        const float* Arow = A + (size_t)pin[s] * Wcols + c;
        float acc = 0.f;
        #pragma unroll
        for (int h = 0; h < HH; h++)
            acc += g_ew[e * HH + h] * Arow[(size_t)h * Cout];
        atomicAdd(&hout[(size_t)pout[d] * Cout + c], acc);
    }
}

__global__ void bias_kernel(int L, const float* __restrict__ bias, int Cout) {
    int M = OutCnt(L);
    float* hout = Hout(L);
    int total = M * Cout;
    int stride = gridDim.x * blockDim.x;
    for (int t = blockIdx.x * blockDim.x + threadIdx.x; t < total; t += stride)
        hout[t] += bias[t % Cout];
}

__global__ void final_kernel(const float* __restrict__ x, const float* __restrict__ b3,
                             float* __restrict__ out) {
    int total = 8 * 1028;
    int stride = gridDim.x * blockDim.x;
    for (int t = blockIdx.x * blockDim.x + threadIdx.x; t < total; t += stride) {
        int b = t / 1028, c = t - b * 1028;
        out[t] = g_out3[t] + b3[c] + x[(size_t)g_nodeB[b] * 1028 + c];
    }
}

// ---------------- launch ----------------
extern "C" void kernel_launch(void* const* d_in, const int* in_sizes, int n_in,
                              void* d_out, int out_size) {
    const float* x   = (const float*)d_in[0];
    const int*   ei  = (const int*)d_in[1];
    const int*   ptr = (const int*)d_in[2];
    const float* W1 = (const float*)d_in[3];
    const float* as1 = (const float*)d_in[4];
    const float* ad1 = (const float*)d_in[5];
    const float* b1 = (const float*)d_in[6];
    const float* W2 = (const float*)d_in[7];
    const float* as2 = (const float*)d_in[8];
    const float* ad2 = (const float*)d_in[9];
    const float* b2 = (const float*)d_in[10];
    const float* W3 = (const float*)d_in[11];
    const float* as3 = (const float*)d_in[12];
    const float* ad3 = (const float*)d_in[13];
    const float* b3 = (const float*)d_in[14];
    float* out = (float*)d_out;

    reset_kernel<<<64, 256>>>();
    mark_kernel<<<1, 32>>>(ptr);
    expand_kernel<<<128, 256>>>(ei, 3);
    expand_kernel<<<128, 256>>>(ei, 2);
    expand_kernel<<<128, 256>>>(ei, 1);
    compact_kernel<<<64, 256>>>();
    build_edges_kernel<<<160, 256>>>(ei);

    // layer 1 (L=0): K=1028, Wcols=768, Cout=128, slope 0.2
    gemm_kernel<<<1024, 256>>>(0, x, W1, 1028, 768);
    coef_kernel<<<256, 256>>>(0, as1, ad1, 768, 128);
    zero_layer_kernel<<<256, 256>>>(0, 128);
    edge_pass1<<<128, 256>>>(0, 0.2f);
    edge_pass2<<<128, 256>>>(0);
    edge_alpha<<<128, 256>>>(0);
    edge_pass3<<<512, 256>>>(0, 768, 128);
    bias_kernel<<<256, 256>>>(0, b1, 128);

    // layer 2 (L=1): K=128, Wcols=1536, Cout=256, slope 0.2
    gemm_kernel<<<1024, 256>>>(1, (const float*)0, W2, 128, 1536);
    coef_kernel<<<256, 256>>>(1, as2, ad2, 1536, 256);
    zero_layer_kernel<<<256, 256>>>(1, 256);
    edge_pass1<<<128, 256>>>(1, 0.2f);
    edge_pass2<<<128, 256>>>(1);
    edge_alpha<<<128, 256>>>(1);
    edge_pass3<<<512, 256>>>(1, 1536, 256);
    bias_kernel<<<256, 256>>>(1, b2, 256);

    // layer 3 (L=2): K=256, Wcols=6168, Cout=1028, slope 0.0
    gemm_kernel<<<1024, 256>>>(2, (const float*)0, W3, 256, 6168);
    coef_kernel<<<256, 256>>>(2, as3, ad3, 6168, 1028);
    zero_layer_kernel<<<256, 256>>>(2, 1028);
    edge_pass1<<<128, 256>>>(2, 0.0f);
    edge_pass2<<<128, 256>>>(2);
    edge_alpha<<<128, 256>>>(2);
    edge_pass3<<<512, 256>>>(2, 6168, 1028);
    final_kernel<<<64, 256>>>(x, b3, out);
}